// round 9
// baseline (speedup 1.0000x reference)
#include <cuda_runtime.h>
#include <cuda_bf16.h>
#include <cuda_fp16.h>
#include <math.h>

// Problem constants (GCN_83081847374393)
#define N_SRC0   50000
#define N_DST0V  20000
#define N_DST1   5000
#define VOCAB    50000
#define EMB      128
#define HID      256
#define OUTD     16
#define WORDS_PER_NODE 50   // (10 * 5)
#define ST0      128        // ELL stride layer 0 (mean deg 15, sigma 3.9 -> safe)
#define ST1      128        // ELL stride layer 1 (mean deg 15)

// -------- scratch (device globals; no allocation allowed) --------
__device__ __half g_t16[(size_t)VOCAB  * EMB];   // 12.8 MB  fp16 word table
__device__ __half g_x0 [(size_t)N_SRC0 * EMB];   // 12.8 MB  fp16 deg_out0-scaled embeddings
__device__ __half g_h1 [(size_t)N_DST0V * HID];  // 10.24 MB fp16 deg_out1-scaled layer-1 out
__device__ int   g_deg_out0[N_SRC0];
__device__ int   g_deg_out1[N_DST0V];
__device__ int   g_cnt0[N_DST0V];                // doubles as deg_in0
__device__ int   g_cnt1[N_DST1];                 // doubles as deg_in1
__device__ int   g_csr0[(size_t)N_DST0V * ST0];  // ELL buckets: src ids per dst
__device__ int   g_csr1[(size_t)N_DST1  * ST1];

// ---------------- init: fp32->fp16 table conversion + zero counters ----------------
// thread t converts 4 floats; low-index threads also zero the counters
__global__ void k_init(const float* __restrict__ table) {
    int t = blockIdx.x * blockDim.x + threadIdx.x;
    size_t i = (size_t)t * 4;
    if (i < (size_t)VOCAB * EMB) {
        float4 v = *(const float4*)(table + i);
        __half2 h0 = __floats2half2_rn(v.x, v.y);
        __half2 h1 = __floats2half2_rn(v.z, v.w);
        uint2 o; o.x = *(unsigned*)&h0; o.y = *(unsigned*)&h1;
        *(uint2*)(g_t16 + i) = o;
    }
    if (t < N_SRC0)  g_deg_out0[t] = 0;
    if (t < N_DST0V) { g_deg_out1[t] = 0; g_cnt0[t] = 0; }
    if (t < N_DST1)  g_cnt1[t] = 0;
}

// ---------------- single edge pass: out-degrees + ELL bucket fill ----------------
__global__ void k_prep(const int* __restrict__ src0, const int* __restrict__ dst0, int e0,
                       const int* __restrict__ src1, const int* __restrict__ dst1, int e1) {
    int base = (blockIdx.x * blockDim.x + threadIdx.x) * 4;
#pragma unroll
    for (int k = 0; k < 4; k++) {
        int i = base + k;
        if (i < e0) {
            int s = src0[i], d = dst0[i];
            atomicAdd(&g_deg_out0[s], 1);
            int p = atomicAdd(&g_cnt0[d], 1);
            if (p < ST0) g_csr0[(size_t)d * ST0 + p] = s;
        }
        if (i < e1) {
            int s = src1[i], d = dst1[i];
            atomicAdd(&g_deg_out1[s], 1);
            int p = atomicAdd(&g_cnt1[d], 1);
            if (p < ST1) g_csr1[(size_t)d * ST1 + p] = s;
        }
    }
}

// ---------------- embedding gather (fp16 rows) + mean + deg_out0 scale -> fp16 ----
// one warp per node; lane handles 4 consecutive halfs (uint2)
__global__ void k_embed(const int* __restrict__ uw, int n_nodes) {
    int warp = (blockIdx.x * blockDim.x + threadIdx.x) >> 5;
    int lane = threadIdx.x & 31;
    if (warp >= n_nodes) return;
    const int* w = uw + (size_t)warp * WORDS_PER_NODE;
    float ax = 0.f, ay = 0.f, az = 0.f, aw = 0.f;
#pragma unroll 5
    for (int j = 0; j < WORDS_PER_NODE; j++) {
        int idx = __ldg(&w[j]);                          // warp-uniform -> broadcast
        uint2 p = *(const uint2*)(g_t16 + (size_t)idx * EMB + lane * 4);
        float2 f0 = __half22float2(*(__half2*)&p.x);
        float2 f1 = __half22float2(*(__half2*)&p.y);
        ax += f0.x; ay += f0.y; az += f1.x; aw += f1.y;
    }
    float sc = rsqrtf(fmaxf((float)g_deg_out0[warp], 1.0f)) * (1.0f / WORDS_PER_NODE);
    __half2 h0 = __floats2half2_rn(ax * sc, ay * sc);
    __half2 h1 = __floats2half2_rn(az * sc, aw * sc);
    uint2 o; o.x = *(unsigned*)&h0; o.y = *(unsigned*)&h1;
    *(uint2*)(g_x0 + (size_t)warp * EMB + lane * 4) = o;
}

// ---------------- fused gather + GEMM1 ----------------
// h1 = relu( (sum_{s in ELL0[row]} x0[s]) * rsqrt(deg_in0) @ W1 + b1 ) * rsqrt(deg_out1)
#define TILE_R 16
__global__ void __launch_bounds__(256) k_gemm1(const float* __restrict__ W1,
                                               const float* __restrict__ b1) {
    __shared__ float s_a[TILE_R][EMB];
    __shared__ float s_sout[TILE_R];
    int tid  = threadIdx.x;
    int wid  = tid >> 5;
    int lane = tid & 31;
    int row0 = blockIdx.x * TILE_R;

    // gather (fp16 rows) + deg_in0 scale into smem A tile (warp per row)
#pragma unroll
    for (int r = wid; r < TILE_R; r += 8) {
        int row = row0 + r;
        const int* bucket = g_csr0 + (size_t)row * ST0;
        int deg = g_cnt0[row];
        int degc = deg < ST0 ? deg : ST0;
        float ax = 0.f, ay = 0.f, az = 0.f, aw = 0.f;
        for (int j = 0; j < degc; j++) {
            int s = bucket[j];                           // lane-uniform -> broadcast
            uint2 p = *(const uint2*)(g_x0 + (size_t)s * EMB + lane * 4);
            float2 f0 = __half22float2(*(__half2*)&p.x);
            float2 f1 = __half22float2(*(__half2*)&p.y);
            ax += f0.x; ay += f0.y; az += f1.x; aw += f1.y;
        }
        float sc = rsqrtf(fmaxf((float)deg, 1.0f));
        float4 o; o.x = ax * sc; o.y = ay * sc; o.z = az * sc; o.w = aw * sc;
        *(float4*)&s_a[r][lane * 4] = o;
    }
    if (tid < TILE_R) s_sout[tid] = rsqrtf(fmaxf((float)g_deg_out1[row0 + tid], 1.0f));
    __syncthreads();

    int c = tid;  // 0..255 output column
    float acc[TILE_R];
#pragma unroll
    for (int r = 0; r < TILE_R; r++) acc[r] = 0.0f;

#pragma unroll 4
    for (int k4 = 0; k4 < EMB / 4; k4++) {
        float w0 = W1[(k4 * 4 + 0) * HID + c];
        float w1 = W1[(k4 * 4 + 1) * HID + c];
        float w2 = W1[(k4 * 4 + 2) * HID + c];
        float w3 = W1[(k4 * 4 + 3) * HID + c];
#pragma unroll
        for (int r = 0; r < TILE_R; r++) {
            float4 a = *(const float4*)&s_a[r][k4 * 4];
            acc[r] = fmaf(a.x, w0, acc[r]);
            acc[r] = fmaf(a.y, w1, acc[r]);
            acc[r] = fmaf(a.z, w2, acc[r]);
            acc[r] = fmaf(a.w, w3, acc[r]);
        }
    }
    float bc = b1[c];
#pragma unroll
    for (int r = 0; r < TILE_R; r++) {
        float v = fmaxf(acc[r] + bc, 0.0f) * s_sout[r];
        g_h1[(size_t)(row0 + r) * HID + c] = __float2half(v);
    }
}

// ---------------- fused gather + GEMM2 -> d_out ----------------
__global__ void __launch_bounds__(256) k_gemm2(const float* __restrict__ W2,
                                               const float* __restrict__ b2,
                                               float* __restrict__ out, int n_rows) {
    __shared__ float s_w[HID * OUTD];   // 16 KB
    __shared__ float s_a[16][HID];      // 16 KB
    int tid  = threadIdx.x;
    int wid  = tid >> 5;
    int lane = tid & 31;
    int row0 = blockIdx.x * 16;

#pragma unroll
    for (int i = tid; i < HID * OUTD; i += 256) s_w[i] = W2[i];

#pragma unroll
    for (int r = wid; r < 16; r += 8) {
        int row = row0 + r;
        if (row < n_rows) {
            const int* bucket = g_csr1 + (size_t)row * ST1;
            int deg = g_cnt1[row];
            int degc = deg < ST1 ? deg : ST1;
            float a0 = 0, a1 = 0, a2 = 0, a3 = 0, a4 = 0, a5 = 0, a6 = 0, a7 = 0;
            for (int j = 0; j < degc; j++) {
                int s = bucket[j];
                uint4 p = *(const uint4*)(g_h1 + (size_t)s * HID + lane * 8);
                float2 f0 = __half22float2(*(__half2*)&p.x);
                float2 f1 = __half22float2(*(__half2*)&p.y);
                float2 f2 = __half22float2(*(__half2*)&p.z);
                float2 f3 = __half22float2(*(__half2*)&p.w);
                a0 += f0.x; a1 += f0.y; a2 += f1.x; a3 += f1.y;
                a4 += f2.x; a5 += f2.y; a6 += f3.x; a7 += f3.y;
            }
            float sc = rsqrtf(fmaxf((float)deg, 1.0f));
            float4 o0; o0.x = a0 * sc; o0.y = a1 * sc; o0.z = a2 * sc; o0.w = a3 * sc;
            float4 o1; o1.x = a4 * sc; o1.y = a5 * sc; o1.z = a6 * sc; o1.w = a7 * sc;
            *(float4*)&s_a[r][lane * 8]     = o0;
            *(float4*)&s_a[r][lane * 8 + 4] = o1;
        }
    }
    __syncthreads();

    int r_local = tid >> 4;
    int c       = tid & 15;
    int row     = row0 + r_local;
    if (row >= n_rows) return;

    float acc = 0.0f;
#pragma unroll 8
    for (int k4 = 0; k4 < HID / 4; k4++) {
        float4 av = *(const float4*)&s_a[r_local][k4 * 4];
        acc = fmaf(av.x, s_w[(k4 * 4 + 0) * OUTD + c], acc);
        acc = fmaf(av.y, s_w[(k4 * 4 + 1) * OUTD + c], acc);
        acc = fmaf(av.z, s_w[(k4 * 4 + 2) * OUTD + c], acc);
        acc = fmaf(av.w, s_w[(k4 * 4 + 3) * OUTD + c], acc);
    }
    out[(size_t)row * OUTD + c] = fmaxf(acc + b2[c], 0.0f);
}

// ---------------- labels tail: cast int labels to float ----------------
__global__ void k_labels(const int* __restrict__ labels, float* __restrict__ out,
                         int offset, int n) {
    int i = blockIdx.x * blockDim.x + threadIdx.x;
    if (i < n) out[offset + i] = (float)labels[i];
}

extern "C" void kernel_launch(void* const* d_in, const int* in_sizes, int n_in,
                              void* d_out, int out_size) {
    const int*   user_word = (const int*)  d_in[0];
    const int*   labels    = (const int*)  d_in[1];
    const int*   src0      = (const int*)  d_in[2];
    const int*   dst0      = (const int*)  d_in[3];
    const int*   src1      = (const int*)  d_in[4];
    const int*   dst1      = (const int*)  d_in[5];
    const float* table     = (const float*)d_in[6];
    const float* W1        = (const float*)d_in[7];
    const float* b1        = (const float*)d_in[8];
    const float* W2        = (const float*)d_in[9];
    const float* b2        = (const float*)d_in[10];
    float* out = (float*)d_out;

    const int n_nodes = in_sizes[0] / WORDS_PER_NODE;  // 50000
    const int n_dst1  = in_sizes[1];                   // 5000
    const int e0      = in_sizes[2];                   // 300000
    const int e1      = in_sizes[4];                   // 75000

    // 1. init: fp16 table + zero counters
    {
        size_t n4 = ((size_t)VOCAB * EMB) / 4;         // 1.6M threads
        k_init<<<(unsigned)((n4 + 255) / 256), 256>>>(table);
    }
    // 2. single edge pass: out-degrees + ELL buckets (cnt == in-degree)
    {
        int n = e0 > e1 ? e0 : e1;
        k_prep<<<(n + 1023) / 1024, 256>>>(src0, dst0, e0, src1, dst1, e1);
    }
    // 3. embedding gather/mean from fp16 table (+deg_out0 scale) -> fp16 x0
    k_embed<<<(n_nodes * 32 + 255) / 256, 256>>>(user_word, n_nodes);
    // 4. fused gather + GEMM1 -> fp16 h1
    k_gemm1<<<N_DST0V / TILE_R, 256>>>(W1, b1);
    // 5. fused gather + GEMM2 -> d_out head
    k_gemm2<<<(n_dst1 + 15) / 16, 256>>>(W2, b2, out, n_dst1);
    // 6. labels tail (as float)
    int feat = n_dst1 * OUTD;
    int nlab = out_size - feat;
    if (nlab > 0) {
        if (nlab > n_dst1) nlab = n_dst1;
        k_labels<<<(nlab + 255) / 256, 256>>>(labels, out, feat, nlab);
    }
}

// round 10
// speedup vs baseline: 1.3134x; 1.3134x over previous
#include <cuda_runtime.h>
#include <cuda_bf16.h>
#include <cuda_fp16.h>
#include <math.h>

// Problem constants (GCN_83081847374393)
#define N_SRC0   50000
#define N_DST0V  20000
#define N_DST1   5000
#define VOCAB    50000
#define EMB      128
#define HID      256
#define OUTD     16
#define WORDS_PER_NODE 50   // (10 * 5)
#define ST0      128        // ELL stride layer 0 (Binomial mean 15, sigma 3.9 -> safe)
#define ST1      128        // ELL stride layer 1 (mean 15)

// -------- scratch (device globals; no allocation allowed) --------
__device__ __half g_t16[(size_t)VOCAB  * EMB];   // 12.8 MB  fp16 word table
__device__ float g_x0 [(size_t)N_SRC0  * EMB];   // 25.6 MB  fp32 deg_out0-scaled embeddings
__device__ float g_h1 [(size_t)N_DST0V * HID];   // 20.48 MB fp32 deg_out1-scaled layer-1 out
__device__ int   g_deg_out0[N_SRC0];
__device__ int   g_deg_out1[N_DST0V];
__device__ int   g_cnt0[N_DST0V];                // doubles as deg_in0
__device__ int   g_cnt1[N_DST1];                 // doubles as deg_in1
__device__ int   g_csr0[(size_t)N_DST0V * ST0];  // ELL buckets: src ids per dst
__device__ int   g_csr1[(size_t)N_DST1  * ST1];

// ---------------- init: fp32->fp16 table conversion + zero counters ----------------
__global__ void k_init(const float* __restrict__ table) {
    int t = blockIdx.x * blockDim.x + threadIdx.x;
    size_t i = (size_t)t * 4;
    if (i < (size_t)VOCAB * EMB) {
        float4 v = *(const float4*)(table + i);
        __half2 h0 = __floats2half2_rn(v.x, v.y);
        __half2 h1 = __floats2half2_rn(v.z, v.w);
        uint2 o; o.x = *(unsigned*)&h0; o.y = *(unsigned*)&h1;
        *(uint2*)(g_t16 + i) = o;
    }
    if (t < N_SRC0)  g_deg_out0[t] = 0;
    if (t < N_DST0V) { g_deg_out1[t] = 0; g_cnt0[t] = 0; }
    if (t < N_DST1)  g_cnt1[t] = 0;
}

// ---------------- single edge pass: out-degrees + ELL bucket fill ----------------
__global__ void k_prep(const int* __restrict__ src0, const int* __restrict__ dst0, int e0,
                       const int* __restrict__ src1, const int* __restrict__ dst1, int e1) {
    int base = (blockIdx.x * blockDim.x + threadIdx.x) * 4;
#pragma unroll
    for (int k = 0; k < 4; k++) {
        int i = base + k;
        if (i < e0) {
            int s = src0[i], d = dst0[i];
            atomicAdd(&g_deg_out0[s], 1);
            int p = atomicAdd(&g_cnt0[d], 1);
            if (p < ST0) g_csr0[(size_t)d * ST0 + p] = s;
        }
        if (i < e1) {
            int s = src1[i], d = dst1[i];
            atomicAdd(&g_deg_out1[s], 1);
            int p = atomicAdd(&g_cnt1[d], 1);
            if (p < ST1) g_csr1[(size_t)d * ST1 + p] = s;
        }
    }
}

// ---------------- embedding gather (fp16 table) + mean + deg_out0 scale -> fp32 ----
// one warp per node; lane handles 4 consecutive halfs (uint2)
__global__ void k_embed(const int* __restrict__ uw, int n_nodes) {
    int warp = (blockIdx.x * blockDim.x + threadIdx.x) >> 5;
    int lane = threadIdx.x & 31;
    if (warp >= n_nodes) return;
    const int* w = uw + (size_t)warp * WORDS_PER_NODE;
    float ax = 0.f, ay = 0.f, az = 0.f, aw = 0.f;
#pragma unroll 5
    for (int j = 0; j < WORDS_PER_NODE; j++) {
        int idx = __ldg(&w[j]);                          // warp-uniform -> broadcast
        uint2 p = *(const uint2*)(g_t16 + (size_t)idx * EMB + lane * 4);
        float2 f0 = __half22float2(*(__half2*)&p.x);
        float2 f1 = __half22float2(*(__half2*)&p.y);
        ax += f0.x; ay += f0.y; az += f1.x; aw += f1.y;
    }
    float sc = rsqrtf(fmaxf((float)g_deg_out0[warp], 1.0f)) * (1.0f / WORDS_PER_NODE);
    float4 o; o.x = ax * sc; o.y = ay * sc; o.z = az * sc; o.w = aw * sc;
    *(float4*)(g_x0 + (size_t)warp * EMB + lane * 4) = o;
}

// ---------------- fused gather + GEMM1 ----------------
// h1 = relu( (sum_{s in ELL0[row]} x0[s]) * rsqrt(deg_in0) @ W1 + b1 ) * rsqrt(deg_out1)
#define TILE_R 16
__global__ void __launch_bounds__(256) k_gemm1(const float* __restrict__ W1,
                                               const float* __restrict__ b1) {
    __shared__ float s_a[TILE_R][EMB];
    __shared__ float s_sout[TILE_R];
    int tid  = threadIdx.x;
    int wid  = tid >> 5;
    int lane = tid & 31;
    int row0 = blockIdx.x * TILE_R;

    // gather + deg_in0 scale into smem A tile (warp per row)
    // indices fetched 32-at-a-time and shfl-broadcast -> data loads pipeline at full MLP
#pragma unroll
    for (int r = wid; r < TILE_R; r += 8) {
        int row = row0 + r;
        const int* bucket = g_csr0 + (size_t)row * ST0;
        int deg  = g_cnt0[row];
        int degc = deg < ST0 ? deg : ST0;
        float ax = 0.f, ay = 0.f, az = 0.f, aw = 0.f;
        for (int j0 = 0; j0 < degc; j0 += 32) {
            int myi = (j0 + lane < degc) ? bucket[j0 + lane] : 0;
            int m = degc - j0; if (m > 32) m = 32;
            for (int jj = 0; jj < m; jj++) {
                int s = __shfl_sync(0xffffffffu, myi, jj);
                const float4 v = *(const float4*)(g_x0 + (size_t)s * EMB + lane * 4);
                ax += v.x; ay += v.y; az += v.z; aw += v.w;
            }
        }
        float sc = rsqrtf(fmaxf((float)deg, 1.0f));
        float4 o; o.x = ax * sc; o.y = ay * sc; o.z = az * sc; o.w = aw * sc;
        *(float4*)&s_a[r][lane * 4] = o;
    }
    if (tid < TILE_R) s_sout[tid] = rsqrtf(fmaxf((float)g_deg_out1[row0 + tid], 1.0f));
    __syncthreads();

    int c = tid;  // 0..255 output column
    float acc[TILE_R];
#pragma unroll
    for (int r = 0; r < TILE_R; r++) acc[r] = 0.0f;

#pragma unroll 4
    for (int k4 = 0; k4 < EMB / 4; k4++) {
        float w0 = W1[(k4 * 4 + 0) * HID + c];
        float w1 = W1[(k4 * 4 + 1) * HID + c];
        float w2 = W1[(k4 * 4 + 2) * HID + c];
        float w3 = W1[(k4 * 4 + 3) * HID + c];
#pragma unroll
        for (int r = 0; r < TILE_R; r++) {
            float4 a = *(const float4*)&s_a[r][k4 * 4];
            acc[r] = fmaf(a.x, w0, acc[r]);
            acc[r] = fmaf(a.y, w1, acc[r]);
            acc[r] = fmaf(a.z, w2, acc[r]);
            acc[r] = fmaf(a.w, w3, acc[r]);
        }
    }
    float bc = b1[c];
#pragma unroll
    for (int r = 0; r < TILE_R; r++) {
        float v = fmaxf(acc[r] + bc, 0.0f) * s_sout[r];
        g_h1[(size_t)(row0 + r) * HID + c] = v;
    }
}

// ---------------- fused gather + GEMM2 -> d_out ----------------
__global__ void __launch_bounds__(256) k_gemm2(const float* __restrict__ W2,
                                               const float* __restrict__ b2,
                                               float* __restrict__ out, int n_rows) {
    __shared__ float s_w[HID * OUTD];   // 16 KB
    __shared__ float s_a[16][HID];      // 16 KB
    int tid  = threadIdx.x;
    int wid  = tid >> 5;
    int lane = tid & 31;
    int row0 = blockIdx.x * 16;

#pragma unroll
    for (int i = tid; i < HID * OUTD; i += 256) s_w[i] = W2[i];

#pragma unroll
    for (int r = wid; r < 16; r += 8) {
        int row = row0 + r;
        if (row < n_rows) {
            const int* bucket = g_csr1 + (size_t)row * ST1;
            int deg  = g_cnt1[row];
            int degc = deg < ST1 ? deg : ST1;
            float a0 = 0, a1 = 0, a2 = 0, a3 = 0, a4 = 0, a5 = 0, a6 = 0, a7 = 0;
            for (int j0 = 0; j0 < degc; j0 += 32) {
                int myi = (j0 + lane < degc) ? bucket[j0 + lane] : 0;
                int m = degc - j0; if (m > 32) m = 32;
                for (int jj = 0; jj < m; jj++) {
                    int s = __shfl_sync(0xffffffffu, myi, jj);
                    const float* sp = g_h1 + (size_t)s * HID + lane * 8;
                    float4 v0 = *(const float4*)(sp);
                    float4 v1 = *(const float4*)(sp + 4);
                    a0 += v0.x; a1 += v0.y; a2 += v0.z; a3 += v0.w;
                    a4 += v1.x; a5 += v1.y; a6 += v1.z; a7 += v1.w;
                }
            }
            float sc = rsqrtf(fmaxf((float)deg, 1.0f));
            float4 o0; o0.x = a0 * sc; o0.y = a1 * sc; o0.z = a2 * sc; o0.w = a3 * sc;
            float4 o1; o1.x = a4 * sc; o1.y = a5 * sc; o1.z = a6 * sc; o1.w = a7 * sc;
            *(float4*)&s_a[r][lane * 8]     = o0;
            *(float4*)&s_a[r][lane * 8 + 4] = o1;
        }
    }
    __syncthreads();

    int r_local = tid >> 4;
    int c       = tid & 15;
    int row     = row0 + r_local;
    if (row >= n_rows) return;

    float acc = 0.0f;
#pragma unroll 8
    for (int k4 = 0; k4 < HID / 4; k4++) {
        float4 av = *(const float4*)&s_a[r_local][k4 * 4];
        acc = fmaf(av.x, s_w[(k4 * 4 + 0) * OUTD + c], acc);
        acc = fmaf(av.y, s_w[(k4 * 4 + 1) * OUTD + c], acc);
        acc = fmaf(av.z, s_w[(k4 * 4 + 2) * OUTD + c], acc);
        acc = fmaf(av.w, s_w[(k4 * 4 + 3) * OUTD + c], acc);
    }
    out[(size_t)row * OUTD + c] = fmaxf(acc + b2[c], 0.0f);
}

// ---------------- labels tail: cast int labels to float ----------------
__global__ void k_labels(const int* __restrict__ labels, float* __restrict__ out,
                         int offset, int n) {
    int i = blockIdx.x * blockDim.x + threadIdx.x;
    if (i < n) out[offset + i] = (float)labels[i];
}

extern "C" void kernel_launch(void* const* d_in, const int* in_sizes, int n_in,
                              void* d_out, int out_size) {
    const int*   user_word = (const int*)  d_in[0];
    const int*   labels    = (const int*)  d_in[1];
    const int*   src0      = (const int*)  d_in[2];
    const int*   dst0      = (const int*)  d_in[3];
    const int*   src1      = (const int*)  d_in[4];
    const int*   dst1      = (const int*)  d_in[5];
    const float* table     = (const float*)d_in[6];
    const float* W1        = (const float*)d_in[7];
    const float* b1        = (const float*)d_in[8];
    const float* W2        = (const float*)d_in[9];
    const float* b2        = (const float*)d_in[10];
    float* out = (float*)d_out;

    const int n_nodes = in_sizes[0] / WORDS_PER_NODE;  // 50000
    const int n_dst1  = in_sizes[1];                   // 5000
    const int e0      = in_sizes[2];                   // 300000
    const int e1      = in_sizes[4];                   // 75000

    // 1. init: fp16 table + zero counters
    {
        size_t n4 = ((size_t)VOCAB * EMB) / 4;
        k_init<<<(unsigned)((n4 + 255) / 256), 256>>>(table);
    }
    // 2. single edge pass: out-degrees + ELL buckets (cnt == in-degree)
    {
        int n = e0 > e1 ? e0 : e1;
        k_prep<<<(n + 1023) / 1024, 256>>>(src0, dst0, e0, src1, dst1, e1);
    }
    // 3. embedding gather/mean from fp16 table (+deg_out0 scale) -> fp32 x0
    k_embed<<<(n_nodes * 32 + 255) / 256, 256>>>(user_word, n_nodes);
    // 4. fused gather + GEMM1 -> fp32 h1
    k_gemm1<<<N_DST0V / TILE_R, 256>>>(W1, b1);
    // 5. fused gather + GEMM2 -> d_out head
    k_gemm2<<<(n_dst1 + 15) / 16, 256>>>(W2, b2, out, n_dst1);
    // 6. labels tail (as float)
    int feat = n_dst1 * OUTD;
    int nlab = out_size - feat;
    if (nlab > 0) {
        if (nlab > n_dst1) nlab = n_dst1;
        k_labels<<<(nlab + 255) / 256, 256>>>(labels, out, feat, nlab);
    }
}

// round 11
// speedup vs baseline: 1.7087x; 1.3010x over previous
#include <cuda_runtime.h>
#include <cuda_bf16.h>
#include <cuda_fp16.h>
#include <math.h>

// Problem constants (GCN_83081847374393)
#define N_SRC0   50000
#define N_DST0V  20000
#define N_DST1   5000
#define VOCAB    50000
#define EMB      128
#define HID      256
#define OUTD     16
#define WORDS_PER_NODE 50   // (10 * 5)
#define ST0      128        // ELL stride layer 0 (Binomial mean 15, sigma 3.9 -> safe)
#define ST1      128        // ELL stride layer 1 (mean 15)

// -------- scratch (device globals; no allocation allowed) --------
__device__ __half g_t16[(size_t)VOCAB  * EMB];   // 12.8 MB  fp16 word table
__device__ __half g_w1t[(size_t)HID * EMB];      // 64 KB    fp16 W1 transposed [N][K]
__device__ float g_x0 [(size_t)N_SRC0  * EMB];   // 25.6 MB  fp32 deg_out0-scaled embeddings
__device__ float g_h1 [(size_t)N_DST0V * HID];   // 20.48 MB fp32 deg_out1-scaled layer-1 out
__device__ int   g_deg_out0[N_SRC0];
__device__ int   g_deg_out1[N_DST0V];
__device__ int   g_cnt0[N_DST0V];                // doubles as deg_in0
__device__ int   g_cnt1[N_DST1];                 // doubles as deg_in1
__device__ int   g_csr0[(size_t)N_DST0V * ST0];  // ELL buckets: src ids per dst
__device__ int   g_csr1[(size_t)N_DST1  * ST1];

// ---------------- init: fp16 table + fp16 W1^T + zero counters ----------------
__global__ void k_init(const float* __restrict__ table, const float* __restrict__ W1) {
    int t = blockIdx.x * blockDim.x + threadIdx.x;
    size_t i = (size_t)t * 4;
    if (i < (size_t)VOCAB * EMB) {
        float4 v = *(const float4*)(table + i);
        __half2 h0 = __floats2half2_rn(v.x, v.y);
        __half2 h1 = __floats2half2_rn(v.z, v.w);
        uint2 o; o.x = *(unsigned*)&h0; o.y = *(unsigned*)&h1;
        *(uint2*)(g_t16 + i) = o;
    }
    if (t < HID * EMB) {                          // W1t[n][k] = W1[k][n]
        int n = t >> 7, k = t & 127;
        g_w1t[t] = __float2half(W1[(size_t)k * HID + n]);
    }
    if (t < N_SRC0)  g_deg_out0[t] = 0;
    if (t < N_DST0V) { g_deg_out1[t] = 0; g_cnt0[t] = 0; }
    if (t < N_DST1)  g_cnt1[t] = 0;
}

// ---------------- single edge pass: out-degrees + ELL bucket fill ----------------
__global__ void k_prep(const int* __restrict__ src0, const int* __restrict__ dst0, int e0,
                       const int* __restrict__ src1, const int* __restrict__ dst1, int e1) {
    int base = (blockIdx.x * blockDim.x + threadIdx.x) * 4;
#pragma unroll
    for (int k = 0; k < 4; k++) {
        int i = base + k;
        if (i < e0) {
            int s = src0[i], d = dst0[i];
            atomicAdd(&g_deg_out0[s], 1);
            int p = atomicAdd(&g_cnt0[d], 1);
            if (p < ST0) g_csr0[(size_t)d * ST0 + p] = s;
        }
        if (i < e1) {
            int s = src1[i], d = dst1[i];
            atomicAdd(&g_deg_out1[s], 1);
            int p = atomicAdd(&g_cnt1[d], 1);
            if (p < ST1) g_csr1[(size_t)d * ST1 + p] = s;
        }
    }
}

// ---------------- embedding gather (fp16 table) + mean + deg_out0 scale -> fp32 ----
__global__ void k_embed(const int* __restrict__ uw, int n_nodes) {
    int warp = (blockIdx.x * blockDim.x + threadIdx.x) >> 5;
    int lane = threadIdx.x & 31;
    if (warp >= n_nodes) return;
    const int* w = uw + (size_t)warp * WORDS_PER_NODE;
    float ax = 0.f, ay = 0.f, az = 0.f, aw = 0.f;
#pragma unroll 5
    for (int j = 0; j < WORDS_PER_NODE; j++) {
        int idx = __ldg(&w[j]);                          // warp-uniform -> broadcast
        uint2 p = *(const uint2*)(g_t16 + (size_t)idx * EMB + lane * 4);
        float2 f0 = __half22float2(*(__half2*)&p.x);
        float2 f1 = __half22float2(*(__half2*)&p.y);
        ax += f0.x; ay += f0.y; az += f1.x; aw += f1.y;
    }
    float sc = rsqrtf(fmaxf((float)g_deg_out0[warp], 1.0f)) * (1.0f / WORDS_PER_NODE);
    float4 o; o.x = ax * sc; o.y = ay * sc; o.z = az * sc; o.w = aw * sc;
    *(float4*)(g_x0 + (size_t)warp * EMB + lane * 4) = o;
}

// ---------------- fused gather + HMMA GEMM1 ----------------
// h1 = relu( (sum ELL0) * rsqrt(deg_in0) @ W1 + b1 ) * rsqrt(deg_out1)
// 32 rows/block, 8 warps; warp w owns output cols [w*32, w*32+32)
#define TILE_R1 32
__global__ void __launch_bounds__(256) k_gemm1(const float* __restrict__ b1) {
    __shared__ __half s_a[TILE_R1][EMB + 8];   // +8 pad: break 256B-stride bank collision
    __shared__ float s_sout[TILE_R1];
    int tid  = threadIdx.x;
    int wid  = tid >> 5;
    int lane = tid & 31;
    int row0 = blockIdx.x * TILE_R1;

    // gather phase: warp per row (4 rows/warp), shfl-broadcast indices, fp32 accum
#pragma unroll
    for (int r = wid; r < TILE_R1; r += 8) {
        int row = row0 + r;
        const int* bucket = g_csr0 + (size_t)row * ST0;
        int deg  = g_cnt0[row];
        int degc = deg < ST0 ? deg : ST0;
        float ax = 0.f, ay = 0.f, az = 0.f, aw = 0.f;
        for (int j0 = 0; j0 < degc; j0 += 32) {
            int myi = (j0 + lane < degc) ? bucket[j0 + lane] : 0;
            int m = degc - j0; if (m > 32) m = 32;
            for (int jj = 0; jj < m; jj++) {
                int s = __shfl_sync(0xffffffffu, myi, jj);
                const float4 v = *(const float4*)(g_x0 + (size_t)s * EMB + lane * 4);
                ax += v.x; ay += v.y; az += v.z; aw += v.w;
            }
        }
        float sc = rsqrtf(fmaxf((float)deg, 1.0f));
        __half2 h0 = __floats2half2_rn(ax * sc, ay * sc);
        __half2 h1 = __floats2half2_rn(az * sc, aw * sc);
        *(__half2*)&s_a[r][lane * 4]     = h0;
        *(__half2*)&s_a[r][lane * 4 + 2] = h1;
    }
    if (tid < TILE_R1) s_sout[tid] = rsqrtf(fmaxf((float)g_deg_out1[row0 + tid], 1.0f));
    __syncthreads();

    // HMMA phase: m16n8k16.f32.f16.f16.f32, 2 m-tiles x 4 n-tiles per warp
    int n0 = wid * 32;
    int qr = lane >> 2;        // t/4
    int qc = (lane & 3) * 2;   // (t%4)*2
    float c[2][4][4];
#pragma unroll
    for (int m = 0; m < 2; m++)
#pragma unroll
        for (int nt = 0; nt < 4; nt++)
#pragma unroll
            for (int x = 0; x < 4; x++) c[m][nt][x] = 0.0f;

#pragma unroll
    for (int ks = 0; ks < 8; ks++) {
        int k0 = ks * 16;
        unsigned a[2][4];
#pragma unroll
        for (int m = 0; m < 2; m++) {
            int mr = m * 16 + qr;
            a[m][0] = *(const unsigned*)&s_a[mr][k0 + qc];
            a[m][1] = *(const unsigned*)&s_a[mr + 8][k0 + qc];
            a[m][2] = *(const unsigned*)&s_a[mr][k0 + qc + 8];
            a[m][3] = *(const unsigned*)&s_a[mr + 8][k0 + qc + 8];
        }
#pragma unroll
        for (int nt = 0; nt < 4; nt++) {
            int n = n0 + nt * 8 + qr;
            unsigned bb0 = *(const unsigned*)(g_w1t + (size_t)n * EMB + k0 + qc);
            unsigned bb1 = *(const unsigned*)(g_w1t + (size_t)n * EMB + k0 + qc + 8);
#pragma unroll
            for (int m = 0; m < 2; m++) {
                asm volatile(
                    "mma.sync.aligned.m16n8k16.row.col.f32.f16.f16.f32 "
                    "{%0,%1,%2,%3}, {%4,%5,%6,%7}, {%8,%9}, {%0,%1,%2,%3};"
                    : "+f"(c[m][nt][0]), "+f"(c[m][nt][1]),
                      "+f"(c[m][nt][2]), "+f"(c[m][nt][3])
                    : "r"(a[m][0]), "r"(a[m][1]), "r"(a[m][2]), "r"(a[m][3]),
                      "r"(bb0), "r"(bb1));
            }
        }
    }

    // epilogue: +bias, relu, *rsqrt(deg_out1), fp32 stores (float2 pairs)
#pragma unroll
    for (int nt = 0; nt < 4; nt++) {
        int col = n0 + nt * 8 + qc;
        float bc0 = b1[col], bc1 = b1[col + 1];
#pragma unroll
        for (int m = 0; m < 2; m++) {
            int rlo = m * 16 + qr, rhi = rlo + 8;
            float s0 = s_sout[rlo], s1 = s_sout[rhi];
            float2 vlo, vhi;
            vlo.x = fmaxf(c[m][nt][0] + bc0, 0.0f) * s0;
            vlo.y = fmaxf(c[m][nt][1] + bc1, 0.0f) * s0;
            vhi.x = fmaxf(c[m][nt][2] + bc0, 0.0f) * s1;
            vhi.y = fmaxf(c[m][nt][3] + bc1, 0.0f) * s1;
            *(float2*)&g_h1[(size_t)(row0 + rlo) * HID + col] = vlo;
            *(float2*)&g_h1[(size_t)(row0 + rhi) * HID + col] = vhi;
        }
    }
}

// ---------------- fused gather + GEMM2 -> d_out ----------------
__global__ void __launch_bounds__(256) k_gemm2(const float* __restrict__ W2,
                                               const float* __restrict__ b2,
                                               float* __restrict__ out, int n_rows) {
    __shared__ float s_w[HID * OUTD];   // 16 KB
    __shared__ float s_a[16][HID];      // 16 KB
    int tid  = threadIdx.x;
    int wid  = tid >> 5;
    int lane = tid & 31;
    int row0 = blockIdx.x * 16;

#pragma unroll
    for (int i = tid; i < HID * OUTD; i += 256) s_w[i] = W2[i];

#pragma unroll
    for (int r = wid; r < 16; r += 8) {
        int row = row0 + r;
        if (row < n_rows) {
            const int* bucket = g_csr1 + (size_t)row * ST1;
            int deg  = g_cnt1[row];
            int degc = deg < ST1 ? deg : ST1;
            float a0 = 0, a1 = 0, a2 = 0, a3 = 0, a4 = 0, a5 = 0, a6 = 0, a7 = 0;
            for (int j0 = 0; j0 < degc; j0 += 32) {
                int myi = (j0 + lane < degc) ? bucket[j0 + lane] : 0;
                int m = degc - j0; if (m > 32) m = 32;
                for (int jj = 0; jj < m; jj++) {
                    int s = __shfl_sync(0xffffffffu, myi, jj);
                    const float* sp = g_h1 + (size_t)s * HID + lane * 8;
                    float4 v0 = *(const float4*)(sp);
                    float4 v1 = *(const float4*)(sp + 4);
                    a0 += v0.x; a1 += v0.y; a2 += v0.z; a3 += v0.w;
                    a4 += v1.x; a5 += v1.y; a6 += v1.z; a7 += v1.w;
                }
            }
            float sc = rsqrtf(fmaxf((float)deg, 1.0f));
            float4 o0; o0.x = a0 * sc; o0.y = a1 * sc; o0.z = a2 * sc; o0.w = a3 * sc;
            float4 o1; o1.x = a4 * sc; o1.y = a5 * sc; o1.z = a6 * sc; o1.w = a7 * sc;
            *(float4*)&s_a[r][lane * 8]     = o0;
            *(float4*)&s_a[r][lane * 8 + 4] = o1;
        }
    }
    __syncthreads();

    int r_local = tid >> 4;
    int c       = tid & 15;
    int row     = row0 + r_local;
    if (row >= n_rows) return;

    float acc = 0.0f;
#pragma unroll 8
    for (int k4 = 0; k4 < HID / 4; k4++) {
        float4 av = *(const float4*)&s_a[r_local][k4 * 4];
        acc = fmaf(av.x, s_w[(k4 * 4 + 0) * OUTD + c], acc);
        acc = fmaf(av.y, s_w[(k4 * 4 + 1) * OUTD + c], acc);
        acc = fmaf(av.z, s_w[(k4 * 4 + 2) * OUTD + c], acc);
        acc = fmaf(av.w, s_w[(k4 * 4 + 3) * OUTD + c], acc);
    }
    out[(size_t)row * OUTD + c] = fmaxf(acc + b2[c], 0.0f);
}

// ---------------- labels tail: cast int labels to float ----------------
__global__ void k_labels(const int* __restrict__ labels, float* __restrict__ out,
                         int offset, int n) {
    int i = blockIdx.x * blockDim.x + threadIdx.x;
    if (i < n) out[offset + i] = (float)labels[i];
}

extern "C" void kernel_launch(void* const* d_in, const int* in_sizes, int n_in,
                              void* d_out, int out_size) {
    const int*   user_word = (const int*)  d_in[0];
    const int*   labels    = (const int*)  d_in[1];
    const int*   src0      = (const int*)  d_in[2];
    const int*   dst0      = (const int*)  d_in[3];
    const int*   src1      = (const int*)  d_in[4];
    const int*   dst1      = (const int*)  d_in[5];
    const float* table     = (const float*)d_in[6];
    const float* W1        = (const float*)d_in[7];
    const float* b1        = (const float*)d_in[8];
    const float* W2        = (const float*)d_in[9];
    const float* b2        = (const float*)d_in[10];
    float* out = (float*)d_out;

    const int n_nodes = in_sizes[0] / WORDS_PER_NODE;  // 50000
    const int n_dst1  = in_sizes[1];                   // 5000
    const int e0      = in_sizes[2];                   // 300000
    const int e1      = in_sizes[4];                   // 75000

    // 1. init: fp16 table + fp16 W1^T + zero counters
    {
        size_t n4 = ((size_t)VOCAB * EMB) / 4;
        k_init<<<(unsigned)((n4 + 255) / 256), 256>>>(table, W1);
    }
    // 2. single edge pass: out-degrees + ELL buckets (cnt == in-degree)
    {
        int n = e0 > e1 ? e0 : e1;
        k_prep<<<(n + 1023) / 1024, 256>>>(src0, dst0, e0, src1, dst1, e1);
    }
    // 3. embedding gather/mean from fp16 table (+deg_out0 scale) -> fp32 x0
    k_embed<<<(n_nodes * 32 + 255) / 256, 256>>>(user_word, n_nodes);
    // 4. fused gather + HMMA GEMM1 -> fp32 h1
    k_gemm1<<<N_DST0V / TILE_R1, 256>>>(b1);
    // 5. fused gather + GEMM2 -> d_out head
    k_gemm2<<<(n_dst1 + 15) / 16, 256>>>(W2, b2, out, n_dst1);
    // 6. labels tail (as float)
    int feat = n_dst1 * OUTD;
    int nlab = out_size - feat;
    if (nlab > 0) {
        if (nlab > n_dst1) nlab = n_dst1;
        k_labels<<<(nlab + 255) / 256, 256>>>(labels, out, feat, nlab);
    }
}

// round 14
// speedup vs baseline: 1.9049x; 1.1148x over previous
#include <cuda_runtime.h>
#include <cuda_bf16.h>
#include <cuda_fp16.h>
#include <math.h>

// Problem constants (GCN_83081847374393)
#define N_SRC0   50000
#define N_DST0V  20000
#define N_DST1   5000
#define VOCAB    50000
#define EMB      128
#define HID      256
#define OUTD     16
#define WORDS_PER_NODE 50   // (10 * 5)
#define ST0      128        // ELL stride layer 0 (Binomial mean 15, sigma 3.9 -> safe)
#define ST1      128        // ELL stride layer 1 (mean 15)

// -------- scratch (device globals; no allocation allowed) --------
__device__ __align__(16) __half g_t16[(size_t)VOCAB  * EMB];   // 12.8 MB fp16 word table
__device__ __align__(16) __half g_w1t[(size_t)HID * EMB];      // 64 KB   fp16 W1^T [N][K]
__device__ __align__(16) __half g_x16[(size_t)N_SRC0 * EMB];   // 12.8 MB fp16 scaled embeddings
__device__ __align__(16) __half g_h16[(size_t)N_DST0V * HID];  // 10.2 MB fp16 scaled layer-1 out
__device__ int   g_deg_out0[N_SRC0];
__device__ int   g_deg_out1[N_DST0V];
__device__ int   g_cnt0[N_DST0V];                // doubles as deg_in0
__device__ int   g_cnt1[N_DST1];                 // doubles as deg_in1
__device__ int   g_csr0[(size_t)N_DST0V * ST0];  // ELL buckets: src ids per dst
__device__ int   g_csr1[(size_t)N_DST1  * ST1];

// ---------------- init: fp16 table + fp16 W1^T + zero counters ----------------
__global__ void k_init(const float* __restrict__ table, const float* __restrict__ W1) {
    int t = blockIdx.x * blockDim.x + threadIdx.x;
    size_t i = (size_t)t * 4;
    if (i < (size_t)VOCAB * EMB) {
        float4 v = *(const float4*)(table + i);
        __half2 h0 = __floats2half2_rn(v.x, v.y);
        __half2 h1 = __floats2half2_rn(v.z, v.w);
        uint2 o; o.x = *(unsigned*)&h0; o.y = *(unsigned*)&h1;
        *(uint2*)(g_t16 + i) = o;
    }
    if (t < HID * EMB) {                          // W1t[n][k] = W1[k][n]
        int n = t >> 7, k = t & 127;
        g_w1t[t] = __float2half(W1[(size_t)k * HID + n]);
    }
    if (t < N_SRC0)  g_deg_out0[t] = 0;
    if (t < N_DST0V) { g_deg_out1[t] = 0; g_cnt0[t] = 0; }
    if (t < N_DST1)  g_cnt1[t] = 0;
}

// ---------------- single edge pass: out-degrees + ELL bucket fill ----------------
__global__ void k_prep(const int* __restrict__ src0, const int* __restrict__ dst0, int e0,
                       const int* __restrict__ src1, const int* __restrict__ dst1, int e1) {
    int base = (blockIdx.x * blockDim.x + threadIdx.x) * 4;
#pragma unroll
    for (int k = 0; k < 4; k++) {
        int i = base + k;
        if (i < e0) {
            int s = src0[i], d = dst0[i];
            atomicAdd(&g_deg_out0[s], 1);
            int p = atomicAdd(&g_cnt0[d], 1);
            if (p < ST0) g_csr0[(size_t)d * ST0 + p] = s;
        }
        if (i < e1) {
            int s = src1[i], d = dst1[i];
            atomicAdd(&g_deg_out1[s], 1);
            int p = atomicAdd(&g_cnt1[d], 1);
            if (p < ST1) g_csr1[(size_t)d * ST1 + p] = s;
        }
    }
}

// ---------------- embedding gather (fp16 table) + mean + deg_out0 scale -> fp16 ----
__global__ void k_embed(const int* __restrict__ uw, int n_nodes) {
    int warp = (blockIdx.x * blockDim.x + threadIdx.x) >> 5;
    int lane = threadIdx.x & 31;
    if (warp >= n_nodes) return;
    const int* w = uw + (size_t)warp * WORDS_PER_NODE;
    float ax = 0.f, ay = 0.f, az = 0.f, aw = 0.f;
#pragma unroll 5
    for (int j = 0; j < WORDS_PER_NODE; j++) {
        int idx = __ldg(&w[j]);                          // warp-uniform -> broadcast
        uint2 p = *(const uint2*)(g_t16 + (size_t)idx * EMB + lane * 4);
        float2 f0 = __half22float2(*(__half2*)&p.x);
        float2 f1 = __half22float2(*(__half2*)&p.y);
        ax += f0.x; ay += f0.y; az += f1.x; aw += f1.y;
    }
    float sc = rsqrtf(fmaxf((float)g_deg_out0[warp], 1.0f)) * (1.0f / WORDS_PER_NODE);
    __half2 h0 = __floats2half2_rn(ax * sc, ay * sc);
    __half2 h1 = __floats2half2_rn(az * sc, aw * sc);
    uint2 o; o.x = *(unsigned*)&h0; o.y = *(unsigned*)&h1;
    *(uint2*)(g_x16 + (size_t)warp * EMB + lane * 4) = o;
}

// ---------------- fused gather + HMMA GEMM1 ----------------
// h1 = relu( (sum ELL0) * rsqrt(deg_in0) @ W1 + b1 ) * rsqrt(deg_out1)
// 32 rows/block, 8 warps. Gather: 2 rows interleaved per warp, fp16 HADD2 accum.
#define TILE_R1 32
__global__ void __launch_bounds__(256) k_gemm1(const float* __restrict__ b1) {
    __shared__ __half s_a[TILE_R1][EMB + 8];   // +8 pad: break 256B-stride bank collision
    __shared__ float s_sout[TILE_R1];
    int tid  = threadIdx.x;
    int wid  = tid >> 5;
    int lane = tid & 31;
    int row0 = blockIdx.x * TILE_R1;

    const __half2 zero2 = __float2half2_rn(0.0f);
#pragma unroll
    for (int pass = 0; pass < 2; pass++) {
        int rA = wid + pass * 16;          // rows rA and rA+8: independent load chains
        int rB = rA + 8;
        const int* bktA = g_csr0 + (size_t)(row0 + rA) * ST0;
        const int* bktB = g_csr0 + (size_t)(row0 + rB) * ST0;
        int degA = g_cnt0[row0 + rA];
        int degB = g_cnt0[row0 + rB];
        int dcA = degA < ST0 ? degA : ST0;
        int dcB = degB < ST0 ? degB : ST0;
        int dmax = dcA > dcB ? dcA : dcB;
        __half2 aA0 = zero2, aA1 = zero2, aB0 = zero2, aB1 = zero2;
        for (int j0 = 0; j0 < dmax; j0 += 32) {
            int iA = (j0 + lane < dcA) ? bktA[j0 + lane] : 0;
            int iB = (j0 + lane < dcB) ? bktB[j0 + lane] : 0;
            int m = dmax - j0; if (m > 32) m = 32;
#pragma unroll 4
            for (int jj = 0; jj < m; jj++) {
                int sA = __shfl_sync(0xffffffffu, iA, jj);
                int sB = __shfl_sync(0xffffffffu, iB, jj);
                if (j0 + jj < dcA) {
                    uint2 p = *(const uint2*)(g_x16 + (size_t)sA * EMB + lane * 4);
                    aA0 = __hadd2(aA0, *(__half2*)&p.x);
                    aA1 = __hadd2(aA1, *(__half2*)&p.y);
                }
                if (j0 + jj < dcB) {
                    uint2 p = *(const uint2*)(g_x16 + (size_t)sB * EMB + lane * 4);
                    aB0 = __hadd2(aB0, *(__half2*)&p.x);
                    aB1 = __hadd2(aB1, *(__half2*)&p.y);
                }
            }
        }
        float scA = rsqrtf(fmaxf((float)degA, 1.0f));
        float scB = rsqrtf(fmaxf((float)degB, 1.0f));
        float2 fA0 = __half22float2(aA0), fA1 = __half22float2(aA1);
        float2 fB0 = __half22float2(aB0), fB1 = __half22float2(aB1);
        __half2 oA0 = __floats2half2_rn(fA0.x * scA, fA0.y * scA);
        __half2 oA1 = __floats2half2_rn(fA1.x * scA, fA1.y * scA);
        __half2 oB0 = __floats2half2_rn(fB0.x * scB, fB0.y * scB);
        __half2 oB1 = __floats2half2_rn(fB1.x * scB, fB1.y * scB);
        *(__half2*)&s_a[rA][lane * 4]     = oA0;
        *(__half2*)&s_a[rA][lane * 4 + 2] = oA1;
        *(__half2*)&s_a[rB][lane * 4]     = oB0;
        *(__half2*)&s_a[rB][lane * 4 + 2] = oB1;
    }
    if (tid < TILE_R1) s_sout[tid] = rsqrtf(fmaxf((float)g_deg_out1[row0 + tid], 1.0f));
    __syncthreads();

    // HMMA phase: m16n8k16.f32.f16.f16.f32, 2 m-tiles x 4 n-tiles per warp
    int n0 = wid * 32;
    int qr = lane >> 2;        // t/4
    int qc = (lane & 3) * 2;   // (t%4)*2
    float c[2][4][4];
#pragma unroll
    for (int m = 0; m < 2; m++)
#pragma unroll
        for (int nt = 0; nt < 4; nt++)
#pragma unroll
            for (int x = 0; x < 4; x++) c[m][nt][x] = 0.0f;

#pragma unroll
    for (int ks = 0; ks < 8; ks++) {
        int k0 = ks * 16;
        unsigned a[2][4];
#pragma unroll
        for (int m = 0; m < 2; m++) {
            int mr = m * 16 + qr;
            a[m][0] = *(const unsigned*)&s_a[mr][k0 + qc];
            a[m][1] = *(const unsigned*)&s_a[mr + 8][k0 + qc];
            a[m][2] = *(const unsigned*)&s_a[mr][k0 + qc + 8];
            a[m][3] = *(const unsigned*)&s_a[mr + 8][k0 + qc + 8];
        }
#pragma unroll
        for (int nt = 0; nt < 4; nt++) {
            int n = n0 + nt * 8 + qr;
            unsigned bb0 = *(const unsigned*)(g_w1t + (size_t)n * EMB + k0 + qc);
            unsigned bb1 = *(const unsigned*)(g_w1t + (size_t)n * EMB + k0 + qc + 8);
#pragma unroll
            for (int m = 0; m < 2; m++) {
                asm volatile(
                    "mma.sync.aligned.m16n8k16.row.col.f32.f16.f16.f32 "
                    "{%0,%1,%2,%3}, {%4,%5,%6,%7}, {%8,%9}, {%0,%1,%2,%3};"
                    : "+f"(c[m][nt][0]), "+f"(c[m][nt][1]),
                      "+f"(c[m][nt][2]), "+f"(c[m][nt][3])
                    : "r"(a[m][0]), "r"(a[m][1]), "r"(a[m][2]), "r"(a[m][3]),
                      "r"(bb0), "r"(bb1));
            }
        }
    }

    // epilogue: +bias, relu, *rsqrt(deg_out1), fp16 stores (half2 pairs)
#pragma unroll
    for (int nt = 0; nt < 4; nt++) {
        int col = n0 + nt * 8 + qc;
        float bc0 = b1[col], bc1 = b1[col + 1];
#pragma unroll
        for (int m = 0; m < 2; m++) {
            int rlo = m * 16 + qr, rhi = rlo + 8;
            float s0 = s_sout[rlo], s1 = s_sout[rhi];
            __half2 vlo = __floats2half2_rn(fmaxf(c[m][nt][0] + bc0, 0.0f) * s0,
                                            fmaxf(c[m][nt][1] + bc1, 0.0f) * s0);
            __half2 vhi = __floats2half2_rn(fmaxf(c[m][nt][2] + bc0, 0.0f) * s1,
                                            fmaxf(c[m][nt][3] + bc1, 0.0f) * s1);
            *(__half2*)&g_h16[(size_t)(row0 + rlo) * HID + col] = vlo;
            *(__half2*)&g_h16[(size_t)(row0 + rhi) * HID + col] = vhi;
        }
    }
}

// ---------------- fused gather + GEMM2 -> d_out ----------------
// 16 rows/block, 8 warps. Gather: 2 rows interleaved per warp, fp16 HADD2 accum.
__global__ void __launch_bounds__(256) k_gemm2(const float* __restrict__ W2,
                                               const float* __restrict__ b2,
                                               float* __restrict__ out, int n_rows) {
    __shared__ float s_w[HID * OUTD];   // 16 KB
    __shared__ float s_a[16][HID];      // 16 KB
    int tid  = threadIdx.x;
    int wid  = tid >> 5;
    int lane = tid & 31;
    int row0 = blockIdx.x * 16;

#pragma unroll
    for (int i = tid; i < HID * OUTD; i += 256) s_w[i] = W2[i];

    {
        int rA = wid, rB = wid + 8;
        int rowA = row0 + rA, rowB = row0 + rB;
        bool okA = rowA < n_rows, okB = rowB < n_rows;
        const int* bktA = g_csr1 + (size_t)rowA * ST1;
        const int* bktB = g_csr1 + (size_t)rowB * ST1;
        int degA = okA ? g_cnt1[rowA] : 0;
        int degB = okB ? g_cnt1[rowB] : 0;
        int dcA = degA < ST1 ? degA : ST1;
        int dcB = degB < ST1 ? degB : ST1;
        int dmax = dcA > dcB ? dcA : dcB;
        const __half2 zero2 = __float2half2_rn(0.0f);
        __half2 aA[4] = {zero2, zero2, zero2, zero2};
        __half2 aB[4] = {zero2, zero2, zero2, zero2};
        for (int j0 = 0; j0 < dmax; j0 += 32) {
            int iA = (j0 + lane < dcA) ? bktA[j0 + lane] : 0;
            int iB = (j0 + lane < dcB) ? bktB[j0 + lane] : 0;
            int m = dmax - j0; if (m > 32) m = 32;
#pragma unroll 4
            for (int jj = 0; jj < m; jj++) {
                int sA = __shfl_sync(0xffffffffu, iA, jj);
                int sB = __shfl_sync(0xffffffffu, iB, jj);
                if (j0 + jj < dcA) {
                    uint4 p = *(const uint4*)(g_h16 + (size_t)sA * HID + lane * 8);
                    aA[0] = __hadd2(aA[0], *(__half2*)&p.x);
                    aA[1] = __hadd2(aA[1], *(__half2*)&p.y);
                    aA[2] = __hadd2(aA[2], *(__half2*)&p.z);
                    aA[3] = __hadd2(aA[3], *(__half2*)&p.w);
                }
                if (j0 + jj < dcB) {
                    uint4 p = *(const uint4*)(g_h16 + (size_t)sB * HID + lane * 8);
                    aB[0] = __hadd2(aB[0], *(__half2*)&p.x);
                    aB[1] = __hadd2(aB[1], *(__half2*)&p.y);
                    aB[2] = __hadd2(aB[2], *(__half2*)&p.z);
                    aB[3] = __hadd2(aB[3], *(__half2*)&p.w);
                }
            }
        }
        float scA = rsqrtf(fmaxf((float)degA, 1.0f));
        float scB = rsqrtf(fmaxf((float)degB, 1.0f));
#pragma unroll
        for (int q = 0; q < 4; q++) {
            float2 fA = __half22float2(aA[q]);
            float2 fB = __half22float2(aB[q]);
            float2 oA; oA.x = fA.x * scA; oA.y = fA.y * scA;
            float2 oB; oB.x = fB.x * scB; oB.y = fB.y * scB;
            *(float2*)&s_a[rA][lane * 8 + q * 2] = oA;
            *(float2*)&s_a[rB][lane * 8 + q * 2] = oB;
        }
    }
    __syncthreads();

    int r_local = tid >> 4;
    int c       = tid & 15;
    int row     = row0 + r_local;
    if (row >= n_rows) return;

    float acc = 0.0f;
#pragma unroll 8
    for (int k4 = 0; k4 < HID / 4; k4++) {
        float4 av = *(const float4*)&s_a[r_local][k4 * 4];
        acc = fmaf(av.x, s_w[(k4 * 4 + 0) * OUTD + c], acc);
        acc = fmaf(av.y, s_w[(k4 * 4 + 1) * OUTD + c], acc);
        acc = fmaf(av.z, s_w[(k4 * 4 + 2) * OUTD + c], acc);
        acc = fmaf(av.w, s_w[(k4 * 4 + 3) * OUTD + c], acc);
    }
    out[(size_t)row * OUTD + c] = fmaxf(acc + b2[c], 0.0f);
}

// ---------------- labels tail: cast int labels to float ----------------
__global__ void k_labels(const int* __restrict__ labels, float* __restrict__ out,
                         int offset, int n) {
    int i = blockIdx.x * blockDim.x + threadIdx.x;
    if (i < n) out[offset + i] = (float)labels[i];
}

extern "C" void kernel_launch(void* const* d_in, const int* in_sizes, int n_in,
                              void* d_out, int out_size) {
    const int*   user_word = (const int*)  d_in[0];
    const int*   labels    = (const int*)  d_in[1];
    const int*   src0      = (const int*)  d_in[2];
    const int*   dst0      = (const int*)  d_in[3];
    const int*   src1      = (const int*)  d_in[4];
    const int*   dst1      = (const int*)  d_in[5];
    const float* table     = (const float*)d_in[6];
    const float* W1        = (const float*)d_in[7];
    const float* b1        = (const float*)d_in[8];
    const float* W2        = (const float*)d_in[9];
    const float* b2        = (const float*)d_in[10];
    float* out = (float*)d_out;

    const int n_nodes = in_sizes[0] / WORDS_PER_NODE;  // 50000
    const int n_dst1  = in_sizes[1];                   // 5000
    const int e0      = in_sizes[2];                   // 300000
    const int e1      = in_sizes[4];                   // 75000

    // 1. init: fp16 table + fp16 W1^T + zero counters
    {
        size_t n4 = ((size_t)VOCAB * EMB) / 4;
        k_init<<<(unsigned)((n4 + 255) / 256), 256>>>(table, W1);
    }
    // 2. single edge pass: out-degrees + ELL buckets (cnt == in-degree)
    {
        int n = e0 > e1 ? e0 : e1;
        k_prep<<<(n + 1023) / 1024, 256>>>(src0, dst0, e0, src1, dst1, e1);
    }
    // 3. embedding gather/mean from fp16 table (+deg_out0 scale) -> fp16 x
    k_embed<<<(n_nodes * 32 + 255) / 256, 256>>>(user_word, n_nodes);
    // 4. fused gather + HMMA GEMM1 -> fp16 h1
    k_gemm1<<<N_DST0V / TILE_R1, 256>>>(b1);
    // 5. fused gather + GEMM2 -> d_out head
    k_gemm2<<<(n_dst1 + 15) / 16, 256>>>(W2, b2, out, n_dst1);
    // 6. labels tail (as float)
    int feat = n_dst1 * OUTD;
    int nlab = out_size - feat;
    if (nlab > 0) {
        if (nlab > n_dst1) nlab = n_dst1;
        k_labels<<<(nlab + 255) / 256, 256>>>(labels, out, feat, nlab);
    }
}